// round 16
// baseline (speedup 1.0000x reference)
#include <cuda_runtime.h>
#include <cuda_fp16.h>
#include <cuda.h>
#include <cstdint>

#define DM   1024
#define NH   16
#define DKH  64
#define BB   4
#define TS   2048
#define MTOT (BB*TS)        // 8192
#define ELEMS (MTOT*DM)     // 8388608

// Scratch (static device memory — no allocation allowed)
__device__ __half g_q[ELEMS];          // [B,H,T,dk] fp16, pre-scaled
__device__ __half g_k[ELEMS];          // [B,H,T,dk] fp16
__device__ __half g_v[ELEMS];          // [B,H,dk,T] fp16 (transposed per head)
__device__ __half g_y[ELEMS];          // [B,T,C] fp16
__device__ __half g_xh[ELEMS];         // x  -> fp16
__device__ __half g_wah[3 * DM * DM];  // w_attn -> fp16
__device__ __half g_wph[DM * DM];      // w_proj -> fp16

__device__ __forceinline__ void mma16(float* d, const unsigned* a,
                                      unsigned b0, unsigned b1) {
    asm volatile(
        "mma.sync.aligned.m16n8k16.row.col.f32.f16.f16.f32 "
        "{%0,%1,%2,%3}, {%4,%5,%6,%7}, {%8,%9}, {%0,%1,%2,%3};\n"
        : "+f"(d[0]), "+f"(d[1]), "+f"(d[2]), "+f"(d[3])
        : "r"(a[0]), "r"(a[1]), "r"(a[2]), "r"(a[3]), "r"(b0), "r"(b1));
}

__device__ __forceinline__ unsigned smem_u32(const void* p) {
    unsigned a;
    asm("{ .reg .u64 t; cvta.to.shared.u64 t, %1; cvt.u32.u64 %0, t; }"
        : "=r"(a) : "l"(p));
    return a;
}
__device__ __forceinline__ void mbar_init(unsigned addr, unsigned cnt) {
    asm volatile("mbarrier.init.shared.b64 [%0], %1;" :: "r"(addr), "r"(cnt) : "memory");
}
__device__ __forceinline__ void mbar_expect(unsigned addr, unsigned bytes) {
    asm volatile("mbarrier.arrive.expect_tx.shared.b64 _, [%0], %1;"
                 :: "r"(addr), "r"(bytes) : "memory");
}
__device__ __forceinline__ void mbar_wait(unsigned addr, unsigned parity) {
    asm volatile(
        "{\n\t.reg .pred P;\n\tWL%=:\n\t"
        "mbarrier.try_wait.parity.acquire.cta.shared::cta.b64 P, [%0], %1;\n\t"
        "@!P bra WL%=;\n\t}"
        :: "r"(addr), "r"(parity) : "memory");
}
__device__ __forceinline__ void tma2d(unsigned dst, const CUtensorMap* m,
                                      int x, int y, unsigned mb) {
    asm volatile(
        "cp.async.bulk.tensor.2d.shared::cta.global.tile.mbarrier::complete_tx::bytes "
        "[%0], [%1, {%2, %3}], [%4];"
        :: "r"(dst), "l"(m), "r"(x), "r"(y), "r"(mb) : "memory");
}

// fp32 -> fp16 (RN) bulk convert
__global__ void f2h(const float2* __restrict__ s, __half2* __restrict__ d, int n2) {
    int i = blockIdx.x * blockDim.x + threadIdx.x;
    if (i < n2) { float2 v = s[i]; d[i] = __floats2half2_rn(v.x, v.y); }
}

// ---------------------------------------------------------------------------
// fp16 GEMM: C[M,N] = A[M,K] @ B[N,K]^T + bias (TMA-fed, SW128 smem).
// BM=BN=128, BK=64; 256 threads = 8 warps, warp tile 64x32 (2m x 4n).
// 3 stages x 32KB, each filled by 2 TMA ops, gated by per-stage mbarrier.
// Fragment LDS: row stride 32 u32, col ^ ((row&7)*4) (conflict-free).
// MODE 0: fp32 row-major + bias.  MODE 1: fp16 q/k [B,H,T,64] (Q*0.125) and
// v transposed [B,H,64,T].
// ---------------------------------------------------------------------------
#define GSTG 3
#define GEMM_SMEM (GSTG * 32768 + 1024)

template <int MODE>
__global__ void __launch_bounds__(256, 2) gemm_h(
    const __grid_constant__ CUtensorMap tmA,
    const __grid_constant__ CUtensorMap tmB,
    const float* __restrict__ bias, float* __restrict__ C,
    __half* __restrict__ qb, __half* __restrict__ kb, __half* __restrict__ vb,
    int M, int N, int K)
{
    extern __shared__ unsigned char rawsm[];
    unsigned* smu = (unsigned*)(((uintptr_t)rawsm + 1023) & ~(uintptr_t)1023);
    __shared__ unsigned long long mbar[GSTG];

    const int tid  = threadIdx.x;
    const int lane = tid & 31;
    const int warp = tid >> 5;
    const int wm = warp >> 2, wn = warp & 3;   // 2 x 4 warp grid
    const int bm = blockIdx.y * 128;
    const int bn = blockIdx.x * 128;
    const int NT = K >> 6;
    const unsigned sb = smem_u32(smu);

    if (tid == 0) {
#pragma unroll
        for (int s = 0; s < GSTG; s++) mbar_init(smem_u32(&mbar[s]), 1);
    }
    __syncthreads();
    if (tid == 0) {
#pragma unroll
        for (int s = 0; s < GSTG; s++) {
            unsigned mb = smem_u32(&mbar[s]);
            mbar_expect(mb, 32768);
            tma2d(sb + s * 32768, &tmA, s * 64, bm, mb);
            tma2d(sb + s * 32768 + 16384, &tmB, s * 64, bn, mb);
        }
    }

    float acc[4][4][4];
#pragma unroll
    for (int mi = 0; mi < 4; mi++)
#pragma unroll
        for (int ni = 0; ni < 4; ni++)
#pragma unroll
            for (int q = 0; q < 4; q++) acc[mi][ni][q] = 0.0f;

    const int c = lane & 3, lr = lane >> 2;
    const unsigned x = (unsigned)(lr * 4);          // SW128 col XOR (u32 units)
    unsigned cx0[4], cx4[4];
#pragma unroll
    for (int kk = 0; kk < 4; kk++) {
        cx0[kk] = ((unsigned)(kk * 8 + c)) ^ x;
        cx4[kk] = ((unsigned)(kk * 8 + c + 4)) ^ x;
    }

    for (int t = 0; t < NT; t++) {
        const int p = t % 3;
        mbar_wait(smem_u32(&mbar[p]), (unsigned)((t / 3) & 1));

        const unsigned* Ap = smu + p * 8192;
        const unsigned* Bp = Ap + 4096;
#pragma unroll
        for (int kk = 0; kk < 4; kk++) {
            unsigned a[4][4], b0[4], b1[4];
#pragma unroll
            for (int mi = 0; mi < 4; mi++) {
                int r = wm * 64 + mi * 16 + lr;
                a[mi][0] = Ap[r * 32 + cx0[kk]];
                a[mi][1] = Ap[(r + 8) * 32 + cx0[kk]];
                a[mi][2] = Ap[r * 32 + cx4[kk]];
                a[mi][3] = Ap[(r + 8) * 32 + cx4[kk]];
            }
#pragma unroll
            for (int ni = 0; ni < 4; ni++) {
                int rB = wn * 32 + ni * 8 + lr;
                b0[ni] = Bp[rB * 32 + cx0[kk]];
                b1[ni] = Bp[rB * 32 + cx4[kk]];
            }
#pragma unroll
            for (int mi = 0; mi < 4; mi++)
#pragma unroll
                for (int ni = 0; ni < 4; ni++)
                    mma16(acc[mi][ni], a[mi], b0[ni], b1[ni]);
        }
        __syncthreads();   // all readers of stage p done before refill
        if (t + 3 < NT && tid == 0) {
            unsigned mb = smem_u32(&mbar[p]);
            mbar_expect(mb, 32768);
            tma2d(sb + p * 32768, &tmA, (t + 3) * 64, bm, mb);
            tma2d(sb + p * 32768 + 16384, &tmB, (t + 3) * 64, bn, mb);
        }
    }

    // Epilogue (identical to R12)
#pragma unroll
    for (int mi = 0; mi < 4; mi++) {
#pragma unroll
        for (int ni = 0; ni < 4; ni++) {
            int row = bm + wm * 64 + mi * 16 + (lane >> 2);
            int col = bn + wn * 32 + ni * 8 + 2 * (lane & 3);
#pragma unroll
            for (int hf = 0; hf < 2; hf++) {
                int r = row + hf * 8;
                float v0 = acc[mi][ni][hf * 2 + 0] + bias[col];
                float v1 = acc[mi][ni][hf * 2 + 1] + bias[col + 1];
                if (MODE == 0) {
                    *(float2*)(C + (size_t)r * N + col) = make_float2(v0, v1);
                } else {
                    int which = col >> 10;          // 0=q,1=k,2=v
                    int cc = col & 1023;
                    int hh = cc >> 6, dd = cc & 63;
                    int bi = r >> 11, tt = r & 2047;
                    if (which == 0) { v0 *= 0.125f; v1 *= 0.125f; }  // 1/sqrt(64)
                    if (which == 2) {
                        size_t off = (((size_t)bi * NH + hh) * DKH + dd) * TS + tt;
                        vb[off]      = __float2half_rn(v0);
                        vb[off + TS] = __float2half_rn(v1);
                    } else {
                        __half* dst = (which == 0) ? qb : kb;
                        size_t off = (((size_t)bi * NH + hh) * TS + tt) * DKH + dd;
                        *(__half2*)(dst + off) = __floats2half2_rn(v0, v1);
                    }
                }
            }
        }
    }
}

// ---------------------------------------------------------------------------
// Flash attention (fp16, fp32 accum), TMA-fed K/V/Q: block = 128 q-rows x
// (head, batch), 256 threads (8 warps x 16 q-rows). K/V tiles of 64 keys,
// double-buffered via mbarriers. Q/K/V smem: SW128 rows (32 u32, col XOR).
// P buffer (Ss) stays linear stride-36. V pre-transposed in gmem [B,H,dk,T].
// ---------------------------------------------------------------------------
#define AST   36
// u32 offsets in aligned smem: Q=0(4096), K=4096(2x2048), V=8192(2x2048), Ss=12288(4608)
#define ATTN_SMEM (16896 * 4 + 1024)

__global__ void __launch_bounds__(256, 2) attn_kernel(
    const __grid_constant__ CUtensorMap tmQ,
    const __grid_constant__ CUtensorMap tmK,
    const __grid_constant__ CUtensorMap tmV,
    __half* __restrict__ yg)
{
    extern __shared__ unsigned char rawsm[];
    unsigned* smu = (unsigned*)(((uintptr_t)rawsm + 1023) & ~(uintptr_t)1023);
    __shared__ unsigned long long mbq, mbkv[2];

    unsigned* Ss = smu + 12288;

    const int tid  = threadIdx.x;
    const int lane = tid & 31;
    const int warp = tid >> 5;
    const int qt = blockIdx.x, h = blockIdx.y, b = blockIdx.z;
    const int head = b * NH + h;
    const int mb_ = warp * 16;
    const int c = lane & 3, lr = lane >> 2;
    const int r = mb_ + lr;
    const unsigned sb = smem_u32(smu);

    const unsigned x = (unsigned)(lr * 4);
    unsigned cx0[4], cx4[4];
#pragma unroll
    for (int kk = 0; kk < 4; kk++) {
        cx0[kk] = ((unsigned)(kk * 8 + c)) ^ x;
        cx4[kk] = ((unsigned)(kk * 8 + c + 4)) ^ x;
    }

    if (tid == 0) {
        mbar_init(smem_u32(&mbq), 1);
        mbar_init(smem_u32(&mbkv[0]), 1);
        mbar_init(smem_u32(&mbkv[1]), 1);
    }
    __syncthreads();
    if (tid == 0) {
        unsigned mq = smem_u32(&mbq);
        mbar_expect(mq, 16384);
        tma2d(sb, &tmQ, 0, head * TS + qt * 128, mq);
#pragma unroll
        for (int bf = 0; bf < 2; bf++) {
            unsigned mk = smem_u32(&mbkv[bf]);
            mbar_expect(mk, 16384);
            tma2d(sb + 16384 + bf * 8192, &tmK, 0, head * TS + bf * 64, mk);
            tma2d(sb + 32768 + bf * 8192, &tmV, bf * 64, head * DKH, mk);
        }
    }

    float accO[8][4];
#pragma unroll
    for (int nf = 0; nf < 8; nf++)
#pragma unroll
        for (int q = 0; q < 4; q++) accO[nf][q] = 0.0f;
    float mrow[2] = {-1e30f, -1e30f};
    float lrow[2] = {0.0f, 0.0f};

    for (int j = 0; j < TS / 64; j++) {
        const int bf = j & 1;
        mbar_wait(smem_u32(&mbkv[bf]), (unsigned)((j >> 1) & 1));
        if (j == 0) mbar_wait(smem_u32(&mbq), 0u);

        const unsigned* Kb = smu + 4096 + bf * 2048;
        const unsigned* Vb = smu + 8192 + bf * 2048;

        // S = Q @ K^T  (16 q-rows x 64 keys per warp), dim in 4 k16 chunks
        float accS[8][4];
#pragma unroll
        for (int nf = 0; nf < 8; nf++)
#pragma unroll
            for (int q = 0; q < 4; q++) accS[nf][q] = 0.0f;

#pragma unroll
        for (int c16 = 0; c16 < 4; c16++) {
            unsigned a[4];
            a[0] = smu[r * 32 + cx0[c16]];
            a[1] = smu[(r + 8) * 32 + cx0[c16]];
            a[2] = smu[r * 32 + cx4[c16]];
            a[3] = smu[(r + 8) * 32 + cx4[c16]];
#pragma unroll
            for (int nf = 0; nf < 8; nf++) {
                int kr = nf * 8 + lr;
                mma16(accS[nf], a, Kb[kr * 32 + cx0[c16]], Kb[kr * 32 + cx4[c16]]);
            }
        }

        // Online softmax (2 rows/thread: r, r+8)
        float tm0 = -1e30f, tm1 = -1e30f;
#pragma unroll
        for (int nf = 0; nf < 8; nf++) {
            tm0 = fmaxf(tm0, fmaxf(accS[nf][0], accS[nf][1]));
            tm1 = fmaxf(tm1, fmaxf(accS[nf][2], accS[nf][3]));
        }
        tm0 = fmaxf(tm0, __shfl_xor_sync(0xffffffffu, tm0, 1));
        tm0 = fmaxf(tm0, __shfl_xor_sync(0xffffffffu, tm0, 2));
        tm1 = fmaxf(tm1, __shfl_xor_sync(0xffffffffu, tm1, 1));
        tm1 = fmaxf(tm1, __shfl_xor_sync(0xffffffffu, tm1, 2));

        float mn0 = fmaxf(mrow[0], tm0), mn1 = fmaxf(mrow[1], tm1);
        float al0 = __expf(mrow[0] - mn0), al1 = __expf(mrow[1] - mn1);

        float s0 = 0.0f, s1 = 0.0f;
#pragma unroll
        for (int nf = 0; nf < 8; nf++) {
            accS[nf][0] = __expf(accS[nf][0] - mn0);
            accS[nf][1] = __expf(accS[nf][1] - mn0);
            accS[nf][2] = __expf(accS[nf][2] - mn1);
            accS[nf][3] = __expf(accS[nf][3] - mn1);
            s0 += accS[nf][0] + accS[nf][1];
            s1 += accS[nf][2] + accS[nf][3];
        }
        s0 += __shfl_xor_sync(0xffffffffu, s0, 1);
        s0 += __shfl_xor_sync(0xffffffffu, s0, 2);
        s1 += __shfl_xor_sync(0xffffffffu, s1, 1);
        s1 += __shfl_xor_sync(0xffffffffu, s1, 2);

        lrow[0] = lrow[0] * al0 + s0;
        lrow[1] = lrow[1] * al1 + s1;
        mrow[0] = mn0; mrow[1] = mn1;

#pragma unroll
        for (int nf = 0; nf < 8; nf++) {
            accO[nf][0] *= al0; accO[nf][1] *= al0;
            accO[nf][2] *= al1; accO[nf][3] *= al1;
        }

        // P -> fp16, warp-private rows of Ss (linear stride-36)
#pragma unroll
        for (int nf = 0; nf < 8; nf++) {
            __half2 p0 = __floats2half2_rn(accS[nf][0], accS[nf][1]);
            __half2 p1 = __floats2half2_rn(accS[nf][2], accS[nf][3]);
            Ss[r * AST + nf * 4 + c]       = *(unsigned*)&p0;
            Ss[(r + 8) * AST + nf * 4 + c] = *(unsigned*)&p1;
        }
        __syncwarp();  // warp-local P round-trip only

        // O += P @ V   (keys in 4 k16 chunks; V rows = dims, SW128)
#pragma unroll
        for (int k16 = 0; k16 < 4; k16++) {
            const int ku = k16 * 8;
            unsigned a[4];
            a[0] = Ss[r * AST + ku + c];
            a[1] = Ss[(r + 8) * AST + ku + c];
            a[2] = Ss[r * AST + ku + c + 4];
            a[3] = Ss[(r + 8) * AST + ku + c + 4];
#pragma unroll
            for (int nf = 0; nf < 8; nf++) {
                int vr = nf * 8 + lr;
                mma16(accO[nf], a, Vb[vr * 32 + cx0[k16]], Vb[vr * 32 + cx4[k16]]);
            }
        }
        __syncthreads();  // all warps done with buf before refill
        if (tid == 0 && j + 2 < TS / 64) {
            unsigned mk = smem_u32(&mbkv[bf]);
            mbar_expect(mk, 16384);
            tma2d(sb + 16384 + bf * 8192, &tmK, 0, head * TS + (j + 2) * 64, mk);
            tma2d(sb + 32768 + bf * 8192, &tmV, (j + 2) * 64, head * DKH, mk);
        }
    }

    // Normalize, write y fp16 [B,T,C]
    float inv0 = 1.0f / lrow[0], inv1 = 1.0f / lrow[1];
    size_t t0 = (size_t)b * TS + (size_t)qt * 128 + r;
#pragma unroll
    for (int nf = 0; nf < 8; nf++) {
        int c0 = nf * 8 + 2 * (lane & 3);
        *(__half2*)(yg + t0 * DM + h * 64 + c0) =
            __floats2half2_rn(accO[nf][0] * inv0, accO[nf][1] * inv0);
        *(__half2*)(yg + (t0 + 8) * DM + h * 64 + c0) =
            __floats2half2_rn(accO[nf][2] * inv1, accO[nf][3] * inv1);
    }
}

// ---------------------------------------------------------------------------
typedef CUresult (CUDAAPI *tmap_enc_t)(
    CUtensorMap*, CUtensorMapDataType, cuuint32_t, void*,
    const cuuint64_t*, const cuuint64_t*, const cuuint32_t*, const cuuint32_t*,
    CUtensorMapInterleave, CUtensorMapSwizzle, CUtensorMapL2promotion,
    CUtensorMapFloatOOBfill);

static void enc2d(tmap_enc_t f, CUtensorMap* m, void* p,
                  unsigned long long d0, unsigned long long d1,
                  unsigned b0, unsigned b1) {
    cuuint64_t dims[2] = {d0, d1};
    cuuint64_t str[1]  = {d0 * 2};          // bytes, fp16
    cuuint32_t box[2]  = {b0, b1};
    cuuint32_t es[2]   = {1, 1};
    f(m, CU_TENSOR_MAP_DATA_TYPE_FLOAT16, 2, p, dims, str, box, es,
      CU_TENSOR_MAP_INTERLEAVE_NONE, CU_TENSOR_MAP_SWIZZLE_128B,
      CU_TENSOR_MAP_L2_PROMOTION_L2_128B, CU_TENSOR_MAP_FLOAT_OOB_FILL_NONE);
}

extern "C" void kernel_launch(void* const* d_in, const int* in_sizes, int n_in,
                              void* d_out, int out_size) {
    const float* x      = (const float*)d_in[0];
    const float* w_attn = (const float*)d_in[1];
    const float* b_attn = (const float*)d_in[2];
    const float* w_proj = (const float*)d_in[3];
    const float* b_proj = (const float*)d_in[4];
    float* out = (float*)d_out;

    __half *qp, *kp, *vp, *yp, *xh, *wah, *wph;
    cudaGetSymbolAddress((void**)&qp, g_q);
    cudaGetSymbolAddress((void**)&kp, g_k);
    cudaGetSymbolAddress((void**)&vp, g_v);
    cudaGetSymbolAddress((void**)&yp, g_y);
    cudaGetSymbolAddress((void**)&xh, g_xh);
    cudaGetSymbolAddress((void**)&wah, g_wah);
    cudaGetSymbolAddress((void**)&wph, g_wph);

    tmap_enc_t enc = nullptr;
    cudaDriverEntryPointQueryResult qr;
    cudaGetDriverEntryPoint("cuTensorMapEncodeTiled", (void**)&enc,
                            cudaEnableDefault, &qr);

    CUtensorMap mA1, mB1, mA0, mB0, mQ, mK, mV;
    enc2d(enc, &mA1, xh,  DM, MTOT,        64, 128);   // x      [8192,1024]
    enc2d(enc, &mB1, wah, DM, 3 * DM,      64, 128);   // w_attn [3072,1024]
    enc2d(enc, &mA0, yp,  DM, MTOT,        64, 128);   // y      [8192,1024]
    enc2d(enc, &mB0, wph, DM, DM,          64, 128);   // w_proj [1024,1024]
    enc2d(enc, &mQ,  qp,  DKH, (unsigned long long)BB * NH * TS, 64, 128);
    enc2d(enc, &mK,  kp,  DKH, (unsigned long long)BB * NH * TS, 64, 64);
    enc2d(enc, &mV,  vp,  TS,  (unsigned long long)BB * NH * DKH, 64, 64);

    cudaFuncSetAttribute(gemm_h<1>, cudaFuncAttributeMaxDynamicSharedMemorySize,
                         GEMM_SMEM);
    cudaFuncSetAttribute(gemm_h<0>, cudaFuncAttributeMaxDynamicSharedMemorySize,
                         GEMM_SMEM);
    cudaFuncSetAttribute(attn_kernel, cudaFuncAttributeMaxDynamicSharedMemorySize,
                         ATTN_SMEM);

    // 0) convert inputs to fp16 (RN)
    f2h<<<ELEMS / 2 / 256, 256>>>((const float2*)x, (__half2*)xh, ELEMS / 2);
    f2h<<<3 * DM * DM / 2 / 256, 256>>>((const float2*)w_attn, (__half2*)wah,
                                        3 * DM * DM / 2);
    f2h<<<DM * DM / 2 / 256, 256>>>((const float2*)w_proj, (__half2*)wph,
                                    DM * DM / 2);

    // 1) QKV projection -> q/k [B,H,T,dk] (Q pre-scaled), v [B,H,dk,T]
    gemm_h<1><<<dim3(3 * DM / 128, MTOT / 128), 256, GEMM_SMEM>>>(
        mA1, mB1, b_attn, nullptr, qp, kp, vp, MTOT, 3 * DM, DM);

    // 2) Flash attention -> y fp16 [B,T,C]
    attn_kernel<<<dim3(TS / 128, NH, BB), 256, ATTN_SMEM>>>(mQ, mK, mV, yp);

    // 3) Output projection -> d_out (fp32 + bias)
    gemm_h<0><<<dim3(DM / 128, MTOT / 128), 256, GEMM_SMEM>>>(
        mA0, mB0, b_proj, out, nullptr, nullptr, nullptr, MTOT, DM, DM);
}